// round 1
// baseline (speedup 1.0000x reference)
#include <cuda_runtime.h>
#include <math.h>

// Problem constants
// N=16384, H=32, G=8, D=128, FF=2, R=4, GROUPS=4, NBAND=32
#define NTOK 16384

// Output layout in d_out (floats), concatenated in reference return order:
//   index_q [N][4][128], index_k [N][128], weights [N][4]
#define OUT_Q_OFF ((size_t)0)
#define OUT_K_OFF ((size_t)NTOK * 512)
#define OUT_W_OFF ((size_t)NTOK * 512 + (size_t)NTOK * 128)

// ---------------------------------------------------------------------------
// Fold mapping (derived from reference reshapes):
//   within a half (dd in [0,64)):  bm = dd>>2, ffhi = (dd>>1)&1, f = dd&1
//   band = f*16 + bm   (in [0,32))
//   feat = ffhi*8 + g  (in [0,16))
// index_{q,k}[.., half*64 + band*2 + r] = sum_feat fold[band][feat]*proj[band][feat][r]
// ---------------------------------------------------------------------------

#define QK_TPB 8   // tokens per block

__global__ __launch_bounds__(256) void qk_kernel(
    const float* __restrict__ q,
    const float* __restrict__ k,
    const float* __restrict__ proj,   // [32][16][2]
    float* __restrict__ out)
{
    // Folded staging buffers; feat-dim stride 17 to avoid bank conflicts
    __shared__ float QF[4 * 2 * 32 * 17];   // [group][half][band][feat(17)]
    __shared__ float KF[2 * 32 * 17];       // [half][band][feat(17)]

    const int tid   = threadIdx.x;
    const int band  = tid & 31;
    const int half  = (tid >> 5) & 1;
    const int group = tid >> 6;

    // Per-thread proj row (band fixed for this thread) -> registers
    float pr0[16], pr1[16];
    {
        const float2* proj2 = (const float2*)proj;   // [band*16+feat] -> (r0,r1)
        #pragma unroll
        for (int f = 0; f < 16; f++) {
            float2 p = __ldg(&proj2[band * 16 + f]);
            pr0[f] = p.x;
            pr1[f] = p.y;
        }
    }

    const int n0 = blockIdx.x * QK_TPB;

    for (int tok = 0; tok < QK_TPB; tok++) {
        const int n = n0 + tok;

        // ---- stage q row [32][128] into folded layout ----
        {
            const float4* q4 = (const float4*)(q + (size_t)n * 4096);
            #pragma unroll
            for (int jj = 0; jj < 4; jj++) {
                const int e4 = tid + 256 * jj;
                const float4 val = q4[e4];
                const int e  = e4 << 2;           // element index in row
                const int h  = e >> 7;            // head
                const int d  = e & 127;
                const int gh = h >> 2;            // g   (feat low part)
                const int gr = h & 3;             // group
                const int hf = d >> 6;            // half
                const int dd = d & 63;
                const int bm = dd >> 2;
                float* base = QF + ((gr * 2 + hf) * 32) * 17;
                // 4 consecutive d: (f,ffhi) = (0,0),(1,0),(0,1),(1,1)
                base[bm * 17        + gh    ] = val.x;
                base[(16 + bm) * 17 + gh    ] = val.y;
                base[bm * 17        + 8 + gh] = val.z;
                base[(16 + bm) * 17 + 8 + gh] = val.w;
            }
        }
        // ---- stage k row [8][128] into folded layout ----
        {
            const float4* k4 = (const float4*)(k + (size_t)n * 1024);
            const float4 val = k4[tid];
            const int e  = tid << 2;
            const int gh = e >> 7;               // kv head g
            const int d  = e & 127;
            const int hf = d >> 6;
            const int dd = d & 63;
            const int bm = dd >> 2;
            float* base = KF + (hf * 32) * 17;
            base[bm * 17        + gh    ] = val.x;
            base[(16 + bm) * 17 + gh    ] = val.y;
            base[bm * 17        + 8 + gh] = val.z;
            base[(16 + bm) * 17 + 8 + gh] = val.w;
        }
        __syncthreads();

        // ---- compute index_q: one (group,half,band) pair per thread ----
        {
            const float* frow = QF + ((group * 2 + half) * 32 + band) * 17;
            float a0 = 0.f, a1 = 0.f;
            #pragma unroll
            for (int f = 0; f < 16; f++) {
                const float v = frow[f];
                a0 = fmaf(v, pr0[f], a0);
                a1 = fmaf(v, pr1[f], a1);
            }
            float2* o = (float2*)(out + OUT_Q_OFF + (size_t)n * 512 +
                                  group * 128 + half * 64 + band * 2);
            *o = make_float2(a0, a1);
        }
        // ---- compute index_k: threads 0..63 ----
        if (tid < 64) {
            const float* frow = KF + (half * 32 + band) * 17;
            float a0 = 0.f, a1 = 0.f;
            #pragma unroll
            for (int f = 0; f < 16; f++) {
                const float v = frow[f];
                a0 = fmaf(v, pr0[f], a0);
                a1 = fmaf(v, pr1[f], a1);
            }
            float2* o = (float2*)(out + OUT_K_OFF + (size_t)n * 128 +
                                  half * 64 + band * 2);
            *o = make_float2(a0, a1);
        }
        __syncthreads();   // protect staging buffers (WAR) for next token
    }
}

// ---------------------------------------------------------------------------
// weights[n][t] = sqrt( sum_{g,r} ( sum_d v[n][g][d] * vt[g*4+t][d][r] )^2 )
// vt held entirely in registers across 256 threads; v streamed via SMEM.
// ---------------------------------------------------------------------------

#define W_TPB 16

__global__ __launch_bounds__(256) void w_kernel(
    const float* __restrict__ v,
    const float* __restrict__ vt,     // [32][128][4]
    float* __restrict__ out)
{
    extern __shared__ float VS[];            // [W_TPB][1024]
    __shared__ float RED[W_TPB][8][4];       // [tok][g][t]

    const int tid  = threadIdx.x;
    const int dseg = tid & 7;                // d = dseg + 8*i
    const int t    = (tid >> 3) & 3;
    const int g    = tid >> 5;
    const int h    = g * 4 + t;

    // vt slice in registers: 16 x float4 (all 4 r at once)
    float4 wt[16];
    {
        const float4* vt4 = (const float4*)vt;   // [h*128 + d]
        #pragma unroll
        for (int i = 0; i < 16; i++)
            wt[i] = __ldg(&vt4[h * 128 + dseg + 8 * i]);
    }

    const int n0 = blockIdx.x * W_TPB;

    // stage W_TPB v rows (coalesced)
    {
        const float4* v4 = (const float4*)(v + (size_t)n0 * 1024);
        float4* vs4 = (float4*)VS;
        #pragma unroll
        for (int j = 0; j < W_TPB; j++)      // W_TPB*1024/4 / 256 = W_TPB
            vs4[tid + 256 * j] = v4[tid + 256 * j];
    }
    __syncthreads();

    for (int tok = 0; tok < W_TPB; tok++) {
        float4 acc = make_float4(0.f, 0.f, 0.f, 0.f);
        const float* vrow = VS + tok * 1024 + g * 128 + dseg;
        #pragma unroll
        for (int i = 0; i < 16; i++) {
            const float f = vrow[8 * i];
            acc.x = fmaf(f, wt[i].x, acc.x);
            acc.y = fmaf(f, wt[i].y, acc.y);
            acc.z = fmaf(f, wt[i].z, acc.z);
            acc.w = fmaf(f, wt[i].w, acc.w);
        }
        // reduce over dseg (lanes differ only in bits 0..2 within the warp)
        #pragma unroll
        for (int m = 1; m <= 4; m <<= 1) {
            acc.x += __shfl_xor_sync(0xffffffffu, acc.x, m);
            acc.y += __shfl_xor_sync(0xffffffffu, acc.y, m);
            acc.z += __shfl_xor_sync(0xffffffffu, acc.z, m);
            acc.w += __shfl_xor_sync(0xffffffffu, acc.w, m);
        }
        if (dseg == 0)
            RED[tok][g][t] = acc.x * acc.x + acc.y * acc.y +
                             acc.z * acc.z + acc.w * acc.w;
    }
    __syncthreads();

    if (tid < 64) {
        const int tok = tid >> 2;
        const int tt  = tid & 3;
        float s = 0.f;
        #pragma unroll
        for (int gg = 0; gg < 8; gg++) s += RED[tok][gg][tt];
        out[OUT_W_OFF + (size_t)(n0 + tok) * 4 + tt] = sqrtf(s);
    }
}

// ---------------------------------------------------------------------------

extern "C" void kernel_launch(void* const* d_in, const int* in_sizes, int n_in,
                              void* d_out, int out_size)
{
    const float* q    = (const float*)d_in[0];   // [16384][32][128]
    const float* k    = (const float*)d_in[1];   // [16384][8][128]
    const float* v    = (const float*)d_in[2];   // [16384][8][128]
    const float* proj = (const float*)d_in[3];   // [32][16][2]
    const float* vt   = (const float*)d_in[4];   // [32][128][4]
    float* out = (float*)d_out;

    static bool attr_set = false;
    if (!attr_set) {
        cudaFuncSetAttribute(w_kernel, cudaFuncAttributeMaxDynamicSharedMemorySize,
                             W_TPB * 1024 * (int)sizeof(float));
        attr_set = true;
    }

    qk_kernel<<<NTOK / QK_TPB, 256>>>(q, k, proj, out);
    w_kernel<<<NTOK / W_TPB, 256, W_TPB * 1024 * sizeof(float)>>>(v, vt, out);
}

// round 2
// speedup vs baseline: 1.2390x; 1.2390x over previous
#include <cuda_runtime.h>
#include <math.h>

// Problem constants: N=16384, H=32, G=8, D=128, FF=2, R=4, GROUPS=4, NBAND=32
#define NTOK 16384
#define QK_TPB 8
#define W_TPB 8
#define NQK (NTOK / QK_TPB)   // 2048 qk blocks
#define NW  (NTOK / W_TPB)    // 2048 w blocks

// Output layout in d_out (floats): index_q [N][4][128], index_k [N][128], weights [N][4]
#define OUT_Q_OFF ((size_t)0)
#define OUT_K_OFF ((size_t)NTOK * 512)
#define OUT_W_OFF ((size_t)NTOK * 512 + (size_t)NTOK * 128)

// smem plan (floats):
//  qk path: QF[2][4*2*32*17]=2*4352, KF[2][2*32*17]=2*1088  -> 10880 floats (43520 B)
//  w  path: VS[8*1024]=8192, RED[8*8*4]=256                 ->  8448 floats (33792 B)
#define SMEM_FLOATS 10880

// Fold mapping (verified R1): for element (h, d) with dd = d&63:
//   bm = dd>>2, ffhi = (dd>>1)&1, fbit = dd&1
//   band = fbit*16 + bm, feat = ffhi*8 + (h>>2)  [q: group = h&3; k: gh = h]
// out[.., half*64 + band*2 + r] = sum_feat folded[band][feat] * proj[band][feat][r]

__global__ __launch_bounds__(256) void fused_kernel(
    const float* __restrict__ q,
    const float* __restrict__ k,
    const float* __restrict__ v,
    const float* __restrict__ proj,   // [32][16][2]
    const float* __restrict__ vt,     // [32][128][4]
    float* __restrict__ out)
{
    extern __shared__ float smem[];
    const int tid = threadIdx.x;

    if (blockIdx.x < NQK) {
        // ================= QK path =================
        float* QF[2] = { smem, smem + 4352 };
        float* KF[2] = { smem + 8704, smem + 8704 + 1088 };

        const int band  = tid & 31;
        const int half  = (tid >> 5) & 1;
        const int group = tid >> 6;

        // proj row for this thread's band -> registers
        float pr0[16], pr1[16];
        {
            const float2* proj2 = (const float2*)proj;
            #pragma unroll
            for (int f = 0; f < 16; f++) {
                float2 p = __ldg(&proj2[band * 16 + f]);
                pr0[f] = p.x; pr1[f] = p.y;
            }
        }

        // scatter-store index components (invariant across jj except head)
        const int bm = tid & 15;
        const int hf = (tid >> 4) & 1;
        const int hbase = tid >> 5;     // + 8*jj gives head

        const int n0 = blockIdx.x * QK_TPB;
        const float4* q4 = (const float4*)q;
        const float4* k4 = (const float4*)k;

        // prefetch token 0
        float4 pq[4]; float4 pk;
        {
            const size_t qb = (size_t)n0 * 1024;
            #pragma unroll
            for (int jj = 0; jj < 4; jj++) pq[jj] = q4[qb + tid + 256 * jj];
            pk = k4[(size_t)n0 * 256 + tid];
        }

        #pragma unroll
        for (int tok = 0; tok < QK_TPB; tok++) {
            const int n = n0 + tok;
            float* QFb = QF[tok & 1];
            float* KFb = KF[tok & 1];

            // scatter q into folded layout
            #pragma unroll
            for (int jj = 0; jj < 4; jj++) {
                const int h  = hbase + 8 * jj;
                const int gh = h >> 2;
                const int gr = h & 3;
                float* base = QFb + ((gr * 2 + hf) * 32) * 17;
                base[bm * 17        + gh    ] = pq[jj].x;
                base[(16 + bm) * 17 + gh    ] = pq[jj].y;
                base[bm * 17        + 8 + gh] = pq[jj].z;
                base[(16 + bm) * 17 + 8 + gh] = pq[jj].w;
            }
            // scatter k
            {
                const int gh = tid >> 5;
                float* base = KFb + (hf * 32) * 17;
                base[bm * 17        + gh    ] = pk.x;
                base[(16 + bm) * 17 + gh    ] = pk.y;
                base[bm * 17        + 8 + gh] = pk.z;
                base[(16 + bm) * 17 + 8 + gh] = pk.w;
            }

            // prefetch next token before the barrier (latency overlap)
            if (tok < QK_TPB - 1) {
                const size_t qb = (size_t)(n + 1) * 1024;
                #pragma unroll
                for (int jj = 0; jj < 4; jj++) pq[jj] = q4[qb + tid + 256 * jj];
                pk = k4[(size_t)(n + 1) * 256 + tid];
            }

            __syncthreads();

            // index_q: one (group, half, band) pair per thread
            {
                const float* frow = QFb + ((group * 2 + half) * 32 + band) * 17;
                float a0 = 0.f, a1 = 0.f;
                #pragma unroll
                for (int f = 0; f < 16; f++) {
                    const float x = frow[f];
                    a0 = fmaf(x, pr0[f], a0);
                    a1 = fmaf(x, pr1[f], a1);
                }
                float2* o = (float2*)(out + OUT_Q_OFF + (size_t)n * 512 +
                                      group * 128 + half * 64 + band * 2);
                *o = make_float2(a0, a1);
            }
            // index_k: threads 0..63
            if (tid < 64) {
                const float* frow = KFb + (half * 32 + band) * 17;
                float a0 = 0.f, a1 = 0.f;
                #pragma unroll
                for (int f = 0; f < 16; f++) {
                    const float x = frow[f];
                    a0 = fmaf(x, pr0[f], a0);
                    a1 = fmaf(x, pr1[f], a1);
                }
                float2* o = (float2*)(out + OUT_K_OFF + (size_t)n * 128 +
                                      half * 64 + band * 2);
                *o = make_float2(a0, a1);
            }
            // single barrier per token: buffer b written at iter i+2 is
            // protected by the barrier at iter i+1 (reads at iter i drained).
        }
    } else {
        // ================= W path =================
        float* VS  = smem;            // [W_TPB][1024]
        float* RED = smem + 8192;     // [tok][g][t]

        const int dseg = tid & 7;
        const int t    = (tid >> 3) & 3;
        const int g    = tid >> 5;
        const int h    = g * 4 + t;

        // vt slice in registers
        float4 wt[16];
        {
            const float4* vt4 = (const float4*)vt;
            #pragma unroll
            for (int i = 0; i < 16; i++)
                wt[i] = __ldg(&vt4[h * 128 + dseg + 8 * i]);
        }

        const int n0 = (blockIdx.x - NQK) * W_TPB;

        // stage W_TPB v rows (coalesced)
        {
            const float4* v4 = (const float4*)v + (size_t)n0 * 256;
            float4* vs4 = (float4*)VS;
            #pragma unroll
            for (int j = 0; j < W_TPB; j++)
                vs4[tid + 256 * j] = v4[tid + 256 * j];
        }
        __syncthreads();

        #pragma unroll
        for (int tok = 0; tok < W_TPB; tok++) {
            // split accumulators to shorten dependent FMA chains
            float4 a = make_float4(0.f, 0.f, 0.f, 0.f);
            float4 b = make_float4(0.f, 0.f, 0.f, 0.f);
            const float* vrow = VS + tok * 1024 + g * 128 + dseg;
            #pragma unroll
            for (int i = 0; i < 16; i += 2) {
                const float f0 = vrow[8 * i];
                const float f1 = vrow[8 * (i + 1)];
                a.x = fmaf(f0, wt[i].x, a.x);     b.x = fmaf(f1, wt[i+1].x, b.x);
                a.y = fmaf(f0, wt[i].y, a.y);     b.y = fmaf(f1, wt[i+1].y, b.y);
                a.z = fmaf(f0, wt[i].z, a.z);     b.z = fmaf(f1, wt[i+1].z, b.z);
                a.w = fmaf(f0, wt[i].w, a.w);     b.w = fmaf(f1, wt[i+1].w, b.w);
            }
            a.x += b.x; a.y += b.y; a.z += b.z; a.w += b.w;
            #pragma unroll
            for (int m = 1; m <= 4; m <<= 1) {
                a.x += __shfl_xor_sync(0xffffffffu, a.x, m);
                a.y += __shfl_xor_sync(0xffffffffu, a.y, m);
                a.z += __shfl_xor_sync(0xffffffffu, a.z, m);
                a.w += __shfl_xor_sync(0xffffffffu, a.w, m);
            }
            if (dseg == 0)
                RED[(tok * 8 + g) * 4 + t] =
                    a.x * a.x + a.y * a.y + a.z * a.z + a.w * a.w;
        }
        __syncthreads();

        if (tid < W_TPB * 4) {
            const int tok = tid >> 2;
            const int tt  = tid & 3;
            float s = 0.f;
            #pragma unroll
            for (int gg = 0; gg < 8; gg++) s += RED[(tok * 8 + gg) * 4 + tt];
            out[OUT_W_OFF + (size_t)(n0 + tok) * 4 + tt] = sqrtf(s);
        }
    }
}

extern "C" void kernel_launch(void* const* d_in, const int* in_sizes, int n_in,
                              void* d_out, int out_size)
{
    const float* q    = (const float*)d_in[0];   // [16384][32][128]
    const float* k    = (const float*)d_in[1];   // [16384][8][128]
    const float* v    = (const float*)d_in[2];   // [16384][8][128]
    const float* proj = (const float*)d_in[3];   // [32][16][2]
    const float* vt   = (const float*)d_in[4];   // [32][128][4]
    float* out = (float*)d_out;

    fused_kernel<<<NQK + NW, 256, SMEM_FLOATS * sizeof(float)>>>(
        q, k, v, proj, vt, out);
}